// round 13
// baseline (speedup 1.0000x reference)
#include <cuda_runtime.h>
#include <cuda_fp16.h>
#include <math.h>
#include <stdint.h>

// ---------------- problem constants ----------------
#define S 2048
#define D 1024
#define H 16
#define HD 64
#define DF 4096
#define NL 2
#define VOCAB 32000
#define HALFW 128
#define ATT_SCALE 0.125f
#define LN_EPS 1e-5f
#define MB_ELT (1024*1024)

// ---------------- scratch (device globals) ----------------
__device__ float  g_x[S * D];
__device__ __half g_h[S * D];
__device__ __half g_qkv[S * 3 * D];
__device__ __half g_att[S * D];
__device__ __half g_ffn[S * DF];
__device__ __half g_wT[NL * 12 * MB_ELT];
__device__ __half g_embT[VOCAB * D];
__device__ float  g_bqkv[NL * 3 * D];

// ---------------- helpers ----------------
__device__ __forceinline__ uint32_t smem_u32(const void* p) {
    uint32_t a;
    asm("{ .reg .u64 t; cvta.to.shared.u64 t, %1; cvt.u32.u64 %0, t; }" : "=r"(a) : "l"(p));
    return a;
}
__device__ __forceinline__ void cp16(uint32_t dst, const void* src) {
    asm volatile("cp.async.cg.shared.global [%0], [%1], 16;" :: "r"(dst), "l"(src));
}
__device__ __forceinline__ void cp_commit() {
    asm volatile("cp.async.commit_group;" ::: "memory");
}
template<int N>
__device__ __forceinline__ void cp_wait() {
    asm volatile("cp.async.wait_group %0;" :: "n"(N) : "memory");
}
__device__ __forceinline__ void ldsm_x4(uint32_t* r, uint32_t addr) {
    asm volatile("ldmatrix.sync.aligned.m8n8.x4.shared.b16 {%0,%1,%2,%3}, [%4];"
        : "=r"(r[0]), "=r"(r[1]), "=r"(r[2]), "=r"(r[3]) : "r"(addr));
}
__device__ __forceinline__ void mma_f16(float* c, const uint32_t* a, const uint32_t* b) {
    asm volatile(
        "mma.sync.aligned.m16n8k16.row.col.f32.f16.f16.f32 "
        "{%0,%1,%2,%3}, {%4,%5,%6,%7}, {%8,%9}, {%0,%1,%2,%3};"
        : "+f"(c[0]), "+f"(c[1]), "+f"(c[2]), "+f"(c[3])
        : "r"(a[0]), "r"(a[1]), "r"(a[2]), "r"(a[3]), "r"(b[0]), "r"(b[1]));
}
__device__ __forceinline__ float gelu_exact(float v) {
    return 0.5f * v * (1.0f + erff(v * 0.70710678118654752f));
}
__device__ __forceinline__ uint32_t pack_half2(float a, float b) {
    __half2 h = __floats2half2_rn(a, b);
    return *(uint32_t*)&h;
}

// ======= BIG GEMM v3b: 128 thr, 4 warps of 64x64, BKT=64, NSTG=3, reg double-buffered ===
// Mainloop waits with cp_wait<0>: both in-flight fills (stages c and c+1) complete at
// iter top, making the ks==3 cross-iteration fragment prefetch from stage c+1 legal.
#define BBM 128
#define BBN 128
#define BBK 64
#define BPADW 36
#define BNSTG 3
#define BSTW ((BBM + BBN) * BPADW)

template<bool OUT_HALF, bool HAS_BIAS, bool DO_GELU, bool DO_RES>
__global__ __launch_bounds__(128, 2) void mma_gemm_big(
    const __half* __restrict__ A, const __half* __restrict__ B,
    const float* __restrict__ bias, const float* __restrict__ res,
    void* __restrict__ Cout, int N_total, int K_total)
{
    extern __shared__ __align__(16) uint32_t smw[];

    const int tid = threadIdx.x;
    const int bm = blockIdx.x * BBM;
    const int bn = blockIdx.y * BBN;
    const int wid = tid >> 5, lane = tid & 31;
    const int wm = (wid & 1) * 64;
    const int wn = (wid >> 1) * 64;
    const int grp = lane >> 2, tig = lane & 3;

    const uint32_t a_base = ((uint32_t)(wm + (lane & 15)) * BPADW + ((lane >> 4) & 1) * 4) * 4;
    const uint32_t b_base = ((uint32_t)(wn + ((lane >> 4) & 1) * 8 + (lane & 7)) * BPADW + ((lane >> 3) & 1) * 4) * 4;

    float acc[4][8][4];
#pragma unroll
    for (int i = 0; i < 4; ++i)
#pragma unroll
        for (int j = 0; j < 8; ++j)
#pragma unroll
            for (int q = 0; q < 4; ++q) acc[i][j][q] = 0.f;

    uint32_t af[2][4][4];
    uint32_t bf[2][8][2];

    const int nIter = K_total / BBK;

    auto fill = [&](int st, int k0) {
        uint32_t* Ast = smw + st * BSTW;
        uint32_t* Bst = Ast + BBM * BPADW;
#pragma unroll
        for (int i = 0; i < 8; ++i) {
            int id = tid + i * 128;
            int row = id >> 3, c = id & 7;
            cp16(smem_u32(Ast + row * BPADW + c * 4), A + (size_t)(bm + row) * K_total + k0 + c * 8);
        }
#pragma unroll
        for (int i = 0; i < 8; ++i) {
            int id = tid + i * 128;
            int row = id >> 3, c = id & 7;
            cp16(smem_u32(Bst + row * BPADW + c * 4), B + (size_t)(bn + row) * K_total + k0 + c * 8);
        }
    };

    auto load_frags = [&](int b, int st, int ks) {
        const uint32_t sa = smem_u32(smw + st * BSTW) + a_base + ks * 32;
        const uint32_t sb = smem_u32(smw + st * BSTW + BBM * BPADW) + b_base + ks * 32;
#pragma unroll
        for (int mt = 0; mt < 4; ++mt)
            ldsm_x4(af[b][mt], sa + (uint32_t)(mt * 16 * BPADW * 4));
#pragma unroll
        for (int p = 0; p < 4; ++p) {
            uint32_t r[4];
            ldsm_x4(r, sb + (uint32_t)(p * 16 * BPADW * 4));
            bf[b][2 * p][0] = r[0]; bf[b][2 * p][1] = r[1];
            bf[b][2 * p + 1][0] = r[2]; bf[b][2 * p + 1][1] = r[3];
        }
    };

    // prologue: fill stages 0..1
#pragma unroll
    for (int s = 0; s < BNSTG - 1; ++s) {
        fill(s, s * BBK);
        cp_commit();
    }
    cp_wait<1>();          // stage 0 ready
    __syncthreads();
    load_frags(0, 0, 0);
    int buf = 0;

    for (int c = 0; c < nIter; ++c) {
        cp_wait<0>();      // stages c AND c+1 both complete (only 2 fills in flight)
        __syncthreads();

        int nk = c + BNSTG - 1;
        if (nk < nIter) fill(nk % BNSTG, nk * BBK);
        cp_commit();

#pragma unroll
        for (int ks = 0; ks < 4; ++ks) {
            if (!(c == nIter - 1 && ks == 3)) {
                int pc  = (ks == 3) ? c + 1 : c;
                int pks = (ks + 1) & 3;
                load_frags(buf ^ 1, pc % BNSTG, pks);
            }
#pragma unroll
            for (int mt = 0; mt < 4; ++mt)
#pragma unroll
                for (int nt = 0; nt < 8; ++nt)
                    mma_f16(acc[mt][nt], af[buf][mt], bf[buf][nt]);
            buf ^= 1;
        }
    }

    // epilogue
#pragma unroll
    for (int mt = 0; mt < 4; ++mt) {
        const int r0 = bm + wm + mt * 16 + grp;
#pragma unroll
        for (int nt = 0; nt < 8; ++nt) {
            const int cn = bn + wn + nt * 8 + tig * 2;
#pragma unroll
            for (int hh = 0; hh < 2; ++hh) {
                const int row = r0 + hh * 8;
                float v0 = acc[mt][nt][hh * 2 + 0];
                float v1 = acc[mt][nt][hh * 2 + 1];
                if (HAS_BIAS) { v0 += __ldg(&bias[cn]); v1 += __ldg(&bias[cn + 1]); }
                if (DO_GELU) { v0 = gelu_exact(v0); v1 = gelu_exact(v1); }
                if (DO_RES) {
                    const float2 rv = *(const float2*)(res + (size_t)row * N_total + cn);
                    v0 += rv.x; v1 += rv.y;
                }
                if (OUT_HALF) {
                    uint32_t hv = pack_half2(v0, v1);
                    *(uint32_t*)((__half*)Cout + (size_t)row * N_total + cn) = hv;
                } else {
                    *(float2*)((float*)Cout + (size_t)row * N_total + cn) = make_float2(v0, v1);
                }
            }
        }
    }
}

// ================= SMALL GEMM (wo/w2): unchanged (proven config) ====
#define BM 128
#define BKT 64
#define PADW 36
#define NSTG 3

template<int BNT, bool OUT_HALF, bool HAS_BIAS, bool DO_GELU, bool DO_RES>
__global__ __launch_bounds__(256, 2) void mma_gemm(
    const __half* __restrict__ A, const __half* __restrict__ B,
    const float* __restrict__ bias, const float* __restrict__ res,
    void* __restrict__ Cout, int N_total, int K_total)
{
    constexpr int NT = (BNT == 128) ? 8 : 4;
    constexpr int NP = NT / 2;
    constexpr int WNW = (BNT == 128) ? 64 : 32;
    constexpr int STW = (BM + BNT) * PADW;

    extern __shared__ __align__(16) uint32_t smw[];

    const int tid = threadIdx.x;
    const int bm = blockIdx.x * BM;
    const int bn = blockIdx.y * BNT;
    const int wid = tid >> 5, lane = tid & 31;
    const int wm = (wid & 3) * 32;
    const int wn = (wid >> 2) * WNW;
    const int grp = lane >> 2, tig = lane & 3;

    const uint32_t a_base = ((uint32_t)(wm + (lane & 15)) * PADW + ((lane >> 4) & 1) * 4) * 4;
    const uint32_t b_base = ((uint32_t)(wn + ((lane >> 4) & 1) * 8 + (lane & 7)) * PADW + ((lane >> 3) & 1) * 4) * 4;

    float acc[2][NT][4];
#pragma unroll
    for (int i = 0; i < 2; ++i)
#pragma unroll
        for (int j = 0; j < NT; ++j)
#pragma unroll
            for (int q = 0; q < 4; ++q) acc[i][j][q] = 0.f;

    const int nIter = K_total / BKT;

    auto fill = [&](int st, int k0) {
        uint32_t* Ast = smw + st * STW;
        uint32_t* Bst = Ast + BM * PADW;
#pragma unroll
        for (int i = 0; i < 4; ++i) {
            int id = tid + i * 256;
            int row = id >> 3, c = id & 7;
            cp16(smem_u32(Ast + row * PADW + c * 4), A + (size_t)(bm + row) * K_total + k0 + c * 8);
        }
#pragma unroll
        for (int i = 0; i < BNT / 32; ++i) {
            int id = tid + i * 256;
            int row = id >> 3, c = id & 7;
            cp16(smem_u32(Bst + row * PADW + c * 4), B + (size_t)(bn + row) * K_total + k0 + c * 8);
        }
    };

#pragma unroll
    for (int s = 0; s < NSTG - 1; ++s) {
        fill(s, s * BKT);
        cp_commit();
    }

    for (int c = 0; c < nIter; ++c) {
        cp_wait<NSTG - 2>();
        __syncthreads();

        int nk = c + NSTG - 1;
        if (nk < nIter) fill(nk % NSTG, nk * BKT);
        cp_commit();

        const uint32_t sa = smem_u32(smw + (c % NSTG) * STW) + a_base;
        const uint32_t sb = smem_u32(smw + (c % NSTG) * STW + BM * PADW) + b_base;
#pragma unroll
        for (int ks = 0; ks < 4; ++ks) {
            uint32_t af[2][4];
#pragma unroll
            for (int mt = 0; mt < 2; ++mt)
                ldsm_x4(af[mt], sa + (uint32_t)(mt * 16 * PADW * 4 + ks * 32));
            uint32_t bfr[NT][2];
#pragma unroll
            for (int p = 0; p < NP; ++p) {
                uint32_t r[4];
                ldsm_x4(r, sb + (uint32_t)(p * 16 * PADW * 4 + ks * 32));
                bfr[2 * p][0] = r[0]; bfr[2 * p][1] = r[1];
                bfr[2 * p + 1][0] = r[2]; bfr[2 * p + 1][1] = r[3];
            }
#pragma unroll
            for (int mt = 0; mt < 2; ++mt)
#pragma unroll
                for (int nt = 0; nt < NT; ++nt)
                    mma_f16(acc[mt][nt], af[mt], bfr[nt]);
        }
    }

#pragma unroll
    for (int mt = 0; mt < 2; ++mt) {
        const int r0 = bm + wm + mt * 16 + grp;
#pragma unroll
        for (int nt = 0; nt < NT; ++nt) {
            const int cn = bn + wn + nt * 8 + tig * 2;
#pragma unroll
            for (int hh = 0; hh < 2; ++hh) {
                const int row = r0 + hh * 8;
                float v0 = acc[mt][nt][hh * 2 + 0];
                float v1 = acc[mt][nt][hh * 2 + 1];
                if (HAS_BIAS) { v0 += __ldg(&bias[cn]); v1 += __ldg(&bias[cn + 1]); }
                if (DO_GELU) { v0 = gelu_exact(v0); v1 = gelu_exact(v1); }
                if (DO_RES) {
                    const float2 rv = *(const float2*)(res + (size_t)row * N_total + cn);
                    v0 += rv.x; v1 += rv.y;
                }
                if (OUT_HALF) {
                    uint32_t hv = pack_half2(v0, v1);
                    *(uint32_t*)((__half*)Cout + (size_t)row * N_total + cn) = hv;
                } else {
                    *(float2*)((float*)Cout + (size_t)row * N_total + cn) = make_float2(v0, v1);
                }
            }
        }
    }
}

// ---------------- fused prep ----------------
#define TP_W  24576
#define TP_E  56576
#define TP_END 56600

__global__ __launch_bounds__(256) void prep_all(
    const float* __restrict__ wq, const float* __restrict__ wk,
    const float* __restrict__ wv, const float* __restrict__ wo,
    const float* __restrict__ w1, const float* __restrict__ w2,
    const float* __restrict__ emb,
    const float* __restrict__ bq, const float* __restrict__ bk,
    const float* __restrict__ bv)
{
    const int b = blockIdx.x;
    const int tid = threadIdx.x;

    if (b < TP_W) {
        __shared__ float t[32][33];
        const int l = b / 12288;
        const int r = b % 12288;
        const float* src;
        __half* dst;
        int R, C, tile;
        __half* base = g_wT + (size_t)l * 12 * MB_ELT;
        if (r < 4096) {
            int w = r >> 10;
            tile = r & 1023;
            R = D; C = D;
            src = (w == 0 ? wq : w == 1 ? wk : w == 2 ? wv : wo) + (size_t)l * D * D;
            dst = base + (size_t)w * MB_ELT;
        } else if (r < 8192) {
            tile = r - 4096;
            R = D; C = DF;
            src = w1 + (size_t)l * D * DF;
            dst = base + 4 * MB_ELT;
        } else {
            tile = r - 8192;
            R = DF; C = D;
            src = w2 + (size_t)l * DF * D;
            dst = base + 8 * MB_ELT;
        }
        const int tc = C >> 5;
        const int r0 = (tile / tc) * 32;
        const int c0 = (tile % tc) * 32;
        const int x = tid & 31, y = tid >> 5;
#pragma unroll
        for (int i = y; i < 32; i += 8) t[i][x] = src[(size_t)(r0 + i) * C + c0 + x];
        __syncthreads();
#pragma unroll
        for (int i = y; i < 32; i += 8)
            dst[(size_t)(c0 + i) * R + r0 + x] = __float2half_rn(t[x][i]);
    } else if (b < TP_E) {
        size_t i0 = (size_t)(b - TP_W) * 1024 + tid * 4;
        float4 v = *(const float4*)(emb + i0);
        uint32_t h0 = pack_half2(v.x, v.y);
        uint32_t h1 = pack_half2(v.z, v.w);
        *(uint2*)(g_embT + i0) = make_uint2(h0, h1);
    } else {
        int idx = (b - TP_E) * 256 + tid;
        if (idx < NL * 3 * D) {
            int l = idx / (3 * D);
            int i = idx % (3 * D);
            float v = (i < D) ? bq[l * D + i] : (i < 2 * D) ? bk[l * D + i - D] : bv[l * D + i - 2 * D];
            g_bqkv[idx] = v;
        }
    }
}

// ---------------- small kernels ----------------
__global__ void embed_kernel(const int* __restrict__ ids,
                             const float* __restrict__ emb,
                             const float* __restrict__ pos) {
    int idx = blockIdx.x * blockDim.x + threadIdx.x;
    if (idx >= S * D) return;
    int s = idx >> 10;
    int d = idx & (D - 1);
    g_x[idx] = emb[(size_t)ids[s] * D + d] + pos[idx];
}

__global__ __launch_bounds__(256) void ln_kernel(const float* __restrict__ x,
                                                 __half* __restrict__ out,
                                                 const float* __restrict__ g,
                                                 const float* __restrict__ b) {
    __shared__ float rs[256], rs2[256];
    int row = blockIdx.x;
    int t = threadIdx.x;
    const float* xr = x + (size_t)row * D;
    float s = 0.f, s2 = 0.f;
#pragma unroll
    for (int i = t; i < D; i += 256) { float v = xr[i]; s += v; s2 += v * v; }
    rs[t] = s; rs2[t] = s2;
    __syncthreads();
    for (int off = 128; off > 0; off >>= 1) {
        if (t < off) { rs[t] += rs[t + off]; rs2[t] += rs2[t + off]; }
        __syncthreads();
    }
    float mu = rs[0] * (1.0f / D);
    float var = rs2[0] * (1.0f / D) - mu * mu;
    float inv = rsqrtf(var + LN_EPS);
    __half* orow = out + (size_t)row * D;
#pragma unroll
    for (int i = t; i < D; i += 256)
        orow[i] = __float2half_rn((xr[i] - mu) * inv * g[i] + b[i]);
}

// ---------------- tiled local attention ----------------
#define TQ 64
#define JW 320
#define SCP 324

__global__ __launch_bounds__(256) void attn_tiled() {
    extern __shared__ __align__(16) float asm_[];
    float* Qs = asm_;
    float* KV = asm_ + 4096;
    float* sc = asm_ + 8192;
    float* invl = sc + 64 * SCP;

    const int q0 = blockIdx.x * TQ;
    const int head = blockIdx.y;
    const int tid = threadIdx.x;
    const int RS = 3 * D;
    const int qoff = head * HD, koff = D + head * HD, voff = 2 * D + head * HD;
    const int jbase = q0 - HALFW;

    for (int i = tid; i < TQ * 16; i += 256) {
        int row = i >> 4, c4 = (i & 15) * 4;
        uint2 u = *(const uint2*)&g_qkv[(size_t)(q0 + row) * RS + qoff + c4];
        float2 f0 = __half22float2(*(__half2*)&u.x);
        float2 f1 = __half22float2(*(__half2*)&u.y);
        float* dst = &Qs[row * 64 + c4];
        dst[0] = f0.x; dst[1] = f0.y; dst[2] = f1.x; dst[3] = f1.y;
    }

    const int ttq = (tid >> 4) << 2;
    const int ttj = (tid & 15) << 2;

#pragma unroll 1
    for (int jt = 0; jt < 5; ++jt) {
        __syncthreads();
        for (int i = tid; i < TQ * 16; i += 256) {
            int row = i >> 4, c4 = (i & 15) * 4;
            int j = jbase + jt * 64 + row;
            j = min(max(j, 0), S - 1);
            uint2 u = *(const uint2*)&g_qkv[(size_t)j * RS + koff + c4];
            float2 f0 = __half22float2(*(__half2*)&u.x);
            float2 f1 = __half22float2(*(__half2*)&u.y);
            float* dst = &KV[row * 64 + c4];
            dst[0] = f0.x; dst[1] = f0.y; dst[2] = f1.x; dst[3] = f1.y;
        }
        __syncthreads();
        float a[4][4];
#pragma unroll
        for (int i = 0; i < 4; ++i)
#pragma unroll
            for (int j = 0; j < 4; ++j) a[i][j] = 0.f;
#pragma unroll
        for (int d = 0; d < 64; d += 4) {
            float4 qv[4], kv[4];
#pragma unroll
            for (int i = 0; i < 4; ++i) {
                qv[i] = *(const float4*)&Qs[(ttq + i) * 64 + d];
                kv[i] = *(const float4*)&KV[(ttj + i) * 64 + d];
            }
#pragma unroll
            for (int i = 0; i < 4; ++i)
#pragma unroll
                for (int j = 0; j < 4; ++j)
                    a[i][j] += qv[i].x * kv[j].x + qv[i].y * kv[j].y +
                               qv[i].z * kv[j].z + qv[i].w * kv[j].w;
        }
#pragma unroll
        for (int i = 0; i < 4; ++i)
#pragma unroll
            for (int j = 0; j < 4; ++j) {
                int qq = ttq + i;
                int jj = jt * 64 + ttj + j;
                int jg = jbase + jj;
                int qg = q0 + qq;
                bool ok = (jg >= 0) && (jg < S) && (abs(qg - jg) <= HALFW);
                sc[qq * SCP + jj] = ok ? a[i][j] * ATT_SCALE : -1e30f;
            }
    }
    __syncthreads();

    const int wid = tid >> 5, lane = tid & 31;
    for (int r = 0; r < 8; ++r) {
        int q = wid * 8 + r;
        float m = -1e30f;
        for (int j = lane; j < JW; j += 32) m = fmaxf(m, sc[q * SCP + j]);
#pragma unroll
        for (int off = 16; off > 0; off >>= 1) m = fmaxf(m, __shfl_xor_sync(0xffffffffu, m, off));
        float s = 0.f;
        for (int j = lane; j < JW; j += 32) {
            float e = __expf(sc[q * SCP + j] - m);
            sc[q * SCP + j] = e;
            s += e;
        }
#pragma unroll
        for (int off = 16; off > 0; off >>= 1) s += __shfl_xor_sync(0xffffffffu, s, off);
        if (lane == 0) invl[q] = 1.0f / s;
    }
    __syncthreads();

    float o[4][4];
#pragma unroll
    for (int i = 0; i < 4; ++i)
#pragma unroll
        for (int j = 0; j < 4; ++j) o[i][j] = 0.f;
#pragma unroll 1
    for (int jt = 0; jt < 5; ++jt) {
        __syncthreads();
        for (int i = tid; i < TQ * 16; i += 256) {
            int row = i >> 4, c4 = (i & 15) * 4;
            int j = jbase + jt * 64 + row;
            j = min(max(j, 0), S - 1);
            uint2 u = *(const uint2*)&g_qkv[(size_t)j * RS + voff + c4];
            float2 f0 = __half22float2(*(__half2*)&u.x);
            float2 f1 = __half22float2(*(__half2*)&u.y);
            float* dst = &KV[row * 64 + c4];
            dst[0] = f0.x; dst[1] = f0.y; dst[2] = f1.x; dst[3] = f1.y;
        }
        __syncthreads();
#pragma unroll 4
        for (int jj = 0; jj < 64; ++jj) {
            float4 vv = *(const float4*)&KV[jj * 64 + ttj];
            float p[4];
#pragma unroll
            for (int i = 0; i < 4; ++i) p[i] = sc[(ttq + i) * SCP + jt * 64 + jj];
#pragma unroll
            for (int i = 0; i < 4; ++i) {
                o[i][0] += p[i] * vv.x;
                o[i][1] += p[i] * vv.y;
                o[i][2] += p[i] * vv.z;
                o[i][3] += p[i] * vv.w;
            }
        }
    }
#pragma unroll
    for (int i = 0; i < 4; ++i) {
        int q = ttq + i;
        float il = invl[q];
        uint32_t h0 = pack_half2(o[i][0] * il, o[i][1] * il);
        uint32_t h1 = pack_half2(o[i][2] * il, o[i][3] * il);
        *(uint2*)&g_att[(size_t)(q0 + q) * D + qoff + ttj] = make_uint2(h0, h1);
    }
}

// ---------------- host ----------------
extern "C" void kernel_launch(void* const* d_in, const int* in_sizes, int n_in,
                              void* d_out, int out_size) {
    const int*   ids   = (const int*)  d_in[0];
    const float* emb   = (const float*)d_in[1];
    const float* pos   = (const float*)d_in[2];
    const float* wq    = (const float*)d_in[3];
    const float* bq    = (const float*)d_in[4];
    const float* wk    = (const float*)d_in[5];
    const float* bk    = (const float*)d_in[6];
    const float* wv    = (const float*)d_in[7];
    const float* bv    = (const float*)d_in[8];
    const float* wo    = (const float*)d_in[9];
    const float* bo    = (const float*)d_in[10];
    const float* w1    = (const float*)d_in[11];
    const float* b1    = (const float*)d_in[12];
    const float* w2    = (const float*)d_in[13];
    const float* b2    = (const float*)d_in[14];
    const float* ln1_g = (const float*)d_in[15];
    const float* ln1_b = (const float*)d_in[16];
    const float* ln2_g = (const float*)d_in[17];
    const float* ln2_b = (const float*)d_in[18];
    const float* out_g = (const float*)d_in[19];
    const float* out_b = (const float*)d_in[20];
    float* logits = (float*)d_out;

    float *x, *bqkv;
    __half *h, *qkv, *att, *ffn, *wT, *embT;
    cudaGetSymbolAddress((void**)&x,    g_x);
    cudaGetSymbolAddress((void**)&h,    g_h);
    cudaGetSymbolAddress((void**)&qkv,  g_qkv);
    cudaGetSymbolAddress((void**)&att,  g_att);
    cudaGetSymbolAddress((void**)&ffn,  g_ffn);
    cudaGetSymbolAddress((void**)&wT,   g_wT);
    cudaGetSymbolAddress((void**)&embT, g_embT);
    cudaGetSymbolAddress((void**)&bqkv, g_bqkv);

    const int BIG_SM = BSTW * 4 * BNSTG;                       // 110592 B
    const int SM64  = (BM + 64) * PADW * 4 * NSTG;             // 82944 B
    const int ATTN_SM = (4096 + 4096 + 64 * SCP + 64) * 4;
    cudaFuncSetAttribute(mma_gemm_big<true,  true,  false, false>, cudaFuncAttributeMaxDynamicSharedMemorySize, BIG_SM);
    cudaFuncSetAttribute(mma_gemm_big<true,  true,  true,  false>, cudaFuncAttributeMaxDynamicSharedMemorySize, BIG_SM);
    cudaFuncSetAttribute(mma_gemm_big<false, false, false, false>, cudaFuncAttributeMaxDynamicSharedMemorySize, BIG_SM);
    cudaFuncSetAttribute(mma_gemm<64, false, true, false, true>,   cudaFuncAttributeMaxDynamicSharedMemorySize, SM64);
    cudaFuncSetAttribute(attn_tiled, cudaFuncAttributeMaxDynamicSharedMemorySize, ATTN_SM);

    prep_all<<<TP_END, 256>>>(wq, wk, wv, wo, w1, w2, emb, bq, bk, bv);
    embed_kernel<<<(S * D + 255) / 256, 256>>>(ids, emb, pos);

    for (int l = 0; l < NL; ++l) {
        __half* base = wT + (size_t)l * 12 * MB_ELT;

        ln_kernel<<<S, 256>>>(x, h, ln1_g + l * D, ln1_b + l * D);

        // qkv (grid 16x24, 128 thr)   <-- launch 3 layer 0: ncu target
        mma_gemm_big<true, true, false, false><<<dim3(S / BBM, 3 * D / BBN), 128, BIG_SM>>>(
            h, base + 0 * MB_ELT, bqkv + (size_t)l * 3 * D, nullptr, qkv, 3 * D, D);

        attn_tiled<<<dim3(S / TQ, H), 256, ATTN_SM>>>();

        mma_gemm<64, false, true, false, true><<<dim3(S / BM, D / 64), 256, SM64>>>(
            att, base + 3 * MB_ELT, bo + (size_t)l * D, x, x, D, D);

        ln_kernel<<<S, 256>>>(x, h, ln2_g + l * D, ln2_b + l * D);

        mma_gemm_big<true, true, true, false><<<dim3(S / BBM, DF / BBN), 128, BIG_SM>>>(
            h, base + 4 * MB_ELT, b1 + (size_t)l * DF, nullptr, ffn, DF, D);

        mma_gemm<64, false, true, false, true><<<dim3(S / BM, D / 64), 256, SM64>>>(
            ffn, base + 8 * MB_ELT, b2 + (size_t)l * D, x, x, D, DF);
    }

    ln_kernel<<<S, 256>>>(x, h, out_g, out_b);

    mma_gemm_big<false, false, false, false><<<dim3(S / BBM, VOCAB / BBN), 128, BIG_SM>>>(
        h, embT, nullptr, nullptr, logits, VOCAB, D);
}

// round 14
// speedup vs baseline: 1.2078x; 1.2078x over previous
#include <cuda_runtime.h>
#include <cuda_fp16.h>
#include <math.h>
#include <stdint.h>

// ---------------- problem constants ----------------
#define S 2048
#define D 1024
#define H 16
#define HD 64
#define DF 4096
#define NL 2
#define VOCAB 32000
#define HALFW 128
#define ATT_SCALE 0.125f
#define LN_EPS 1e-5f
#define MB_ELT (1024*1024)

// ---------------- scratch (device globals) ----------------
__device__ float  g_x[S * D];
__device__ __half g_h[S * D];
__device__ __half g_qkv[S * 3 * D];
__device__ __half g_att[S * D];
__device__ __half g_ffn[S * DF];
__device__ __half g_wT[NL * 12 * MB_ELT];
__device__ __half g_embT[VOCAB * D];
__device__ float  g_bqkv[NL * 3 * D];

// ---------------- helpers ----------------
__device__ __forceinline__ uint32_t smem_u32(const void* p) {
    uint32_t a;
    asm("{ .reg .u64 t; cvta.to.shared.u64 t, %1; cvt.u32.u64 %0, t; }" : "=r"(a) : "l"(p));
    return a;
}
__device__ __forceinline__ void cp16(uint32_t dst, const void* src) {
    asm volatile("cp.async.cg.shared.global [%0], [%1], 16;" :: "r"(dst), "l"(src));
}
__device__ __forceinline__ void cp_commit() {
    asm volatile("cp.async.commit_group;" ::: "memory");
}
template<int N>
__device__ __forceinline__ void cp_wait() {
    asm volatile("cp.async.wait_group %0;" :: "n"(N) : "memory");
}
__device__ __forceinline__ void ldsm_x4(uint32_t* r, uint32_t addr) {
    asm volatile("ldmatrix.sync.aligned.m8n8.x4.shared.b16 {%0,%1,%2,%3}, [%4];"
        : "=r"(r[0]), "=r"(r[1]), "=r"(r[2]), "=r"(r[3]) : "r"(addr));
}
__device__ __forceinline__ void mma_f16(float* c, const uint32_t* a, const uint32_t* b) {
    asm volatile(
        "mma.sync.aligned.m16n8k16.row.col.f32.f16.f16.f32 "
        "{%0,%1,%2,%3}, {%4,%5,%6,%7}, {%8,%9}, {%0,%1,%2,%3};"
        : "+f"(c[0]), "+f"(c[1]), "+f"(c[2]), "+f"(c[3])
        : "r"(a[0]), "r"(a[1]), "r"(a[2]), "r"(a[3]), "r"(b[0]), "r"(b[1]));
}
__device__ __forceinline__ float gelu_exact(float v) {
    return 0.5f * v * (1.0f + erff(v * 0.70710678118654752f));
}
__device__ __forceinline__ uint32_t pack_half2(float a, float b) {
    __half2 h = __floats2half2_rn(a, b);
    return *(uint32_t*)&h;
}

// ======= BIG GEMM (R11 config): 128 thr, 4 warps of 64x64, BKT=32, NSTG=4, reg dbuf =====
#define BBM 128
#define BBN 128
#define BBK 32
#define BPADW 20
#define BNSTG 4
#define BSTW ((BBM + BBN) * BPADW)

template<bool OUT_HALF, bool HAS_BIAS, bool DO_GELU, bool DO_RES>
__global__ __launch_bounds__(128, 2) void mma_gemm_big(
    const __half* __restrict__ A, const __half* __restrict__ B,
    const float* __restrict__ bias, const float* __restrict__ res,
    void* __restrict__ Cout, int N_total, int K_total)
{
    extern __shared__ __align__(16) uint32_t smw[];

    const int tid = threadIdx.x;
    const int bm = blockIdx.x * BBM;
    const int bn = blockIdx.y * BBN;
    const int wid = tid >> 5, lane = tid & 31;
    const int wm = (wid & 1) * 64;
    const int wn = (wid >> 1) * 64;
    const int grp = lane >> 2, tig = lane & 3;

    const uint32_t a_base = ((uint32_t)(wm + (lane & 15)) * BPADW + ((lane >> 4) & 1) * 4) * 4;
    const uint32_t b_base = ((uint32_t)(wn + ((lane >> 4) & 1) * 8 + (lane & 7)) * BPADW + ((lane >> 3) & 1) * 4) * 4;

    float acc[4][8][4];
#pragma unroll
    for (int i = 0; i < 4; ++i)
#pragma unroll
        for (int j = 0; j < 8; ++j)
#pragma unroll
            for (int q = 0; q < 4; ++q) acc[i][j][q] = 0.f;

    uint32_t af[2][4][4];
    uint32_t bf[2][8][2];

    const int nIter = K_total / BBK;

    auto fill = [&](int st, int k0) {
        uint32_t* Ast = smw + st * BSTW;
        uint32_t* Bst = Ast + BBM * BPADW;
#pragma unroll
        for (int i = 0; i < 4; ++i) {
            int id = tid + i * 128;
            int row = id >> 2, c = id & 3;
            cp16(smem_u32(Ast + row * BPADW + c * 4), A + (size_t)(bm + row) * K_total + k0 + c * 8);
        }
#pragma unroll
        for (int i = 0; i < 4; ++i) {
            int id = tid + i * 128;
            int row = id >> 2, c = id & 3;
            cp16(smem_u32(Bst + row * BPADW + c * 4), B + (size_t)(bn + row) * K_total + k0 + c * 8);
        }
    };

    auto load_frags = [&](int b, int st, int ks) {
        const uint32_t sa = smem_u32(smw + st * BSTW) + a_base + ks * 32;
        const uint32_t sb = smem_u32(smw + st * BSTW + BBM * BPADW) + b_base + ks * 32;
#pragma unroll
        for (int mt = 0; mt < 4; ++mt)
            ldsm_x4(af[b][mt], sa + (uint32_t)(mt * 16 * BPADW * 4));
#pragma unroll
        for (int p = 0; p < 4; ++p) {
            uint32_t r[4];
            ldsm_x4(r, sb + (uint32_t)(p * 16 * BPADW * 4));
            bf[b][2 * p][0] = r[0]; bf[b][2 * p][1] = r[1];
            bf[b][2 * p + 1][0] = r[2]; bf[b][2 * p + 1][1] = r[3];
        }
    };

    // prologue: fill stages 0..2
#pragma unroll
    for (int s = 0; s < BNSTG - 1; ++s) {
        fill(s, s * BBK);
        cp_commit();
    }
    cp_wait<2>();          // stage 0 ready
    __syncthreads();
    load_frags(0, 0, 0);
    int buf = 0;

    for (int c = 0; c < nIter; ++c) {
        cp_wait<1>();      // stages <= c+1 ready
        __syncthreads();

        int nk = c + BNSTG - 1;
        if (nk < nIter) fill(nk % BNSTG, nk * BBK);
        cp_commit();

#pragma unroll
        for (int ks = 0; ks < 2; ++ks) {
            if (!(c == nIter - 1 && ks == 1)) {
                int pc  = (ks == 1) ? c + 1 : c;
                int pks = (ks == 1) ? 0 : 1;
                load_frags(buf ^ 1, pc % BNSTG, pks);
            }
#pragma unroll
            for (int mt = 0; mt < 4; ++mt)
#pragma unroll
                for (int nt = 0; nt < 8; ++nt)
                    mma_f16(acc[mt][nt], af[buf][mt], bf[buf][nt]);
            buf ^= 1;
        }
    }

    // epilogue
#pragma unroll
    for (int mt = 0; mt < 4; ++mt) {
        const int r0 = bm + wm + mt * 16 + grp;
#pragma unroll
        for (int nt = 0; nt < 8; ++nt) {
            const int cn = bn + wn + nt * 8 + tig * 2;
#pragma unroll
            for (int hh = 0; hh < 2; ++hh) {
                const int row = r0 + hh * 8;
                float v0 = acc[mt][nt][hh * 2 + 0];
                float v1 = acc[mt][nt][hh * 2 + 1];
                if (HAS_BIAS) { v0 += __ldg(&bias[cn]); v1 += __ldg(&bias[cn + 1]); }
                if (DO_GELU) { v0 = gelu_exact(v0); v1 = gelu_exact(v1); }
                if (DO_RES) {
                    const float2 rv = *(const float2*)(res + (size_t)row * N_total + cn);
                    v0 += rv.x; v1 += rv.y;
                }
                if (OUT_HALF) {
                    uint32_t hv = pack_half2(v0, v1);
                    *(uint32_t*)((__half*)Cout + (size_t)row * N_total + cn) = hv;
                } else {
                    *(float2*)((float*)Cout + (size_t)row * N_total + cn) = make_float2(v0, v1);
                }
            }
        }
    }
}

// ================= SMALL GEMM (wo/w2): unchanged (proven config) ====
#define BM 128
#define BKT 64
#define PADW 36
#define NSTG 3

template<int BNT, bool OUT_HALF, bool HAS_BIAS, bool DO_GELU, bool DO_RES>
__global__ __launch_bounds__(256, 2) void mma_gemm(
    const __half* __restrict__ A, const __half* __restrict__ B,
    const float* __restrict__ bias, const float* __restrict__ res,
    void* __restrict__ Cout, int N_total, int K_total)
{
    constexpr int NT = (BNT == 128) ? 8 : 4;
    constexpr int NP = NT / 2;
    constexpr int WNW = (BNT == 128) ? 64 : 32;
    constexpr int STW = (BM + BNT) * PADW;

    extern __shared__ __align__(16) uint32_t smw[];

    const int tid = threadIdx.x;
    const int bm = blockIdx.x * BM;
    const int bn = blockIdx.y * BNT;
    const int wid = tid >> 5, lane = tid & 31;
    const int wm = (wid & 3) * 32;
    const int wn = (wid >> 2) * WNW;
    const int grp = lane >> 2, tig = lane & 3;

    const uint32_t a_base = ((uint32_t)(wm + (lane & 15)) * PADW + ((lane >> 4) & 1) * 4) * 4;
    const uint32_t b_base = ((uint32_t)(wn + ((lane >> 4) & 1) * 8 + (lane & 7)) * PADW + ((lane >> 3) & 1) * 4) * 4;

    float acc[2][NT][4];
#pragma unroll
    for (int i = 0; i < 2; ++i)
#pragma unroll
        for (int j = 0; j < NT; ++j)
#pragma unroll
            for (int q = 0; q < 4; ++q) acc[i][j][q] = 0.f;

    const int nIter = K_total / BKT;

    auto fill = [&](int st, int k0) {
        uint32_t* Ast = smw + st * STW;
        uint32_t* Bst = Ast + BM * PADW;
#pragma unroll
        for (int i = 0; i < 4; ++i) {
            int id = tid + i * 256;
            int row = id >> 3, c = id & 7;
            cp16(smem_u32(Ast + row * PADW + c * 4), A + (size_t)(bm + row) * K_total + k0 + c * 8);
        }
#pragma unroll
        for (int i = 0; i < BNT / 32; ++i) {
            int id = tid + i * 256;
            int row = id >> 3, c = id & 7;
            cp16(smem_u32(Bst + row * PADW + c * 4), B + (size_t)(bn + row) * K_total + k0 + c * 8);
        }
    };

#pragma unroll
    for (int s = 0; s < NSTG - 1; ++s) {
        fill(s, s * BKT);
        cp_commit();
    }

    for (int c = 0; c < nIter; ++c) {
        cp_wait<NSTG - 2>();
        __syncthreads();

        int nk = c + NSTG - 1;
        if (nk < nIter) fill(nk % NSTG, nk * BKT);
        cp_commit();

        const uint32_t sa = smem_u32(smw + (c % NSTG) * STW) + a_base;
        const uint32_t sb = smem_u32(smw + (c % NSTG) * STW + BM * PADW) + b_base;
#pragma unroll
        for (int ks = 0; ks < 4; ++ks) {
            uint32_t af[2][4];
#pragma unroll
            for (int mt = 0; mt < 2; ++mt)
                ldsm_x4(af[mt], sa + (uint32_t)(mt * 16 * PADW * 4 + ks * 32));
            uint32_t bfr[NT][2];
#pragma unroll
            for (int p = 0; p < NP; ++p) {
                uint32_t r[4];
                ldsm_x4(r, sb + (uint32_t)(p * 16 * PADW * 4 + ks * 32));
                bfr[2 * p][0] = r[0]; bfr[2 * p][1] = r[1];
                bfr[2 * p + 1][0] = r[2]; bfr[2 * p + 1][1] = r[3];
            }
#pragma unroll
            for (int mt = 0; mt < 2; ++mt)
#pragma unroll
                for (int nt = 0; nt < NT; ++nt)
                    mma_f16(acc[mt][nt], af[mt], bfr[nt]);
        }
    }

#pragma unroll
    for (int mt = 0; mt < 2; ++mt) {
        const int r0 = bm + wm + mt * 16 + grp;
#pragma unroll
        for (int nt = 0; nt < NT; ++nt) {
            const int cn = bn + wn + nt * 8 + tig * 2;
#pragma unroll
            for (int hh = 0; hh < 2; ++hh) {
                const int row = r0 + hh * 8;
                float v0 = acc[mt][nt][hh * 2 + 0];
                float v1 = acc[mt][nt][hh * 2 + 1];
                if (HAS_BIAS) { v0 += __ldg(&bias[cn]); v1 += __ldg(&bias[cn + 1]); }
                if (DO_GELU) { v0 = gelu_exact(v0); v1 = gelu_exact(v1); }
                if (DO_RES) {
                    const float2 rv = *(const float2*)(res + (size_t)row * N_total + cn);
                    v0 += rv.x; v1 += rv.y;
                }
                if (OUT_HALF) {
                    uint32_t hv = pack_half2(v0, v1);
                    *(uint32_t*)((__half*)Cout + (size_t)row * N_total + cn) = hv;
                } else {
                    *(float2*)((float*)Cout + (size_t)row * N_total + cn) = make_float2(v0, v1);
                }
            }
        }
    }
}

// ---------------- fused prep ----------------
#define TP_W  24576
#define TP_E  56576
#define TP_END 56600

__global__ __launch_bounds__(256) void prep_all(
    const float* __restrict__ wq, const float* __restrict__ wk,
    const float* __restrict__ wv, const float* __restrict__ wo,
    const float* __restrict__ w1, const float* __restrict__ w2,
    const float* __restrict__ emb,
    const float* __restrict__ bq, const float* __restrict__ bk,
    const float* __restrict__ bv)
{
    const int b = blockIdx.x;
    const int tid = threadIdx.x;

    if (b < TP_W) {
        __shared__ float t[32][33];
        const int l = b / 12288;
        const int r = b % 12288;
        const float* src;
        __half* dst;
        int R, C, tile;
        __half* base = g_wT + (size_t)l * 12 * MB_ELT;
        if (r < 4096) {
            int w = r >> 10;
            tile = r & 1023;
            R = D; C = D;
            src = (w == 0 ? wq : w == 1 ? wk : w == 2 ? wv : wo) + (size_t)l * D * D;
            dst = base + (size_t)w * MB_ELT;
        } else if (r < 8192) {
            tile = r - 4096;
            R = D; C = DF;
            src = w1 + (size_t)l * D * DF;
            dst = base + 4 * MB_ELT;
        } else {
            tile = r - 8192;
            R = DF; C = D;
            src = w2 + (size_t)l * DF * D;
            dst = base + 8 * MB_ELT;
        }
        const int tc = C >> 5;
        const int r0 = (tile / tc) * 32;
        const int c0 = (tile % tc) * 32;
        const int x = tid & 31, y = tid >> 5;
#pragma unroll
        for (int i = y; i < 32; i += 8) t[i][x] = src[(size_t)(r0 + i) * C + c0 + x];
        __syncthreads();
#pragma unroll
        for (int i = y; i < 32; i += 8)
            dst[(size_t)(c0 + i) * R + r0 + x] = __float2half_rn(t[x][i]);
    } else if (b < TP_E) {
        size_t i0 = (size_t)(b - TP_W) * 1024 + tid * 4;
        float4 v = *(const float4*)(emb + i0);
        uint32_t h0 = pack_half2(v.x, v.y);
        uint32_t h1 = pack_half2(v.z, v.w);
        *(uint2*)(g_embT + i0) = make_uint2(h0, h1);
    } else {
        int idx = (b - TP_E) * 256 + tid;
        if (idx < NL * 3 * D) {
            int l = idx / (3 * D);
            int i = idx % (3 * D);
            float v = (i < D) ? bq[l * D + i] : (i < 2 * D) ? bk[l * D + i - D] : bv[l * D + i - 2 * D];
            g_bqkv[idx] = v;
        }
    }
}

// ---------------- small kernels ----------------
__global__ void embed_kernel(const int* __restrict__ ids,
                             const float* __restrict__ emb,
                             const float* __restrict__ pos) {
    int idx = blockIdx.x * blockDim.x + threadIdx.x;
    if (idx >= S * D) return;
    int s = idx >> 10;
    int d = idx & (D - 1);
    g_x[idx] = emb[(size_t)ids[s] * D + d] + pos[idx];
}

__global__ __launch_bounds__(256) void ln_kernel(const float* __restrict__ x,
                                                 __half* __restrict__ out,
                                                 const float* __restrict__ g,
                                                 const float* __restrict__ b) {
    __shared__ float rs[256], rs2[256];
    int row = blockIdx.x;
    int t = threadIdx.x;
    const float* xr = x + (size_t)row * D;
    float s = 0.f, s2 = 0.f;
#pragma unroll
    for (int i = t; i < D; i += 256) { float v = xr[i]; s += v; s2 += v * v; }
    rs[t] = s; rs2[t] = s2;
    __syncthreads();
    for (int off = 128; off > 0; off >>= 1) {
        if (t < off) { rs[t] += rs[t + off]; rs2[t] += rs2[t + off]; }
        __syncthreads();
    }
    float mu = rs[0] * (1.0f / D);
    float var = rs2[0] * (1.0f / D) - mu * mu;
    float inv = rsqrtf(var + LN_EPS);
    __half* orow = out + (size_t)row * D;
#pragma unroll
    for (int i = t; i < D; i += 256)
        orow[i] = __float2half_rn((xr[i] - mu) * inv * g[i] + b[i]);
}

// ---------------- tiled local attention (K/V tiles kept in half: 2 CTAs/SM) ----------------
#define TQ 64
#define JW 320
#define SCP 324

__global__ __launch_bounds__(256, 2) void attn_tiled() {
    extern __shared__ __align__(16) float asm_[];
    float*  Qs  = asm_;                          // [64][64] float (16KB)
    __half* KVh = (__half*)(asm_ + 4096);        // [64][64] half (8KB)
    float*  sc  = asm_ + 4096 + 2048;            // [64][SCP] (82.9KB)
    float*  invl = sc + 64 * SCP;                // [64]

    const int q0 = blockIdx.x * TQ;
    const int head = blockIdx.y;
    const int tid = threadIdx.x;
    const int RS = 3 * D;
    const int qoff = head * HD, koff = D + head * HD, voff = 2 * D + head * HD;
    const int jbase = q0 - HALFW;

    // load Q tile (half -> float)
    for (int i = tid; i < TQ * 16; i += 256) {
        int row = i >> 4, c4 = (i & 15) * 4;
        uint2 u = *(const uint2*)&g_qkv[(size_t)(q0 + row) * RS + qoff + c4];
        float2 f0 = __half22float2(*(__half2*)&u.x);
        float2 f1 = __half22float2(*(__half2*)&u.y);
        float* dst = &Qs[row * 64 + c4];
        dst[0] = f0.x; dst[1] = f0.y; dst[2] = f1.x; dst[3] = f1.y;
    }

    const int ttq = (tid >> 4) << 2;
    const int ttj = (tid & 15) << 2;

    // ---- scores ----
#pragma unroll 1
    for (int jt = 0; jt < 5; ++jt) {
        __syncthreads();
        for (int i = tid; i < TQ * 16; i += 256) {
            int row = i >> 4, c4 = (i & 15) * 4;
            int j = jbase + jt * 64 + row;
            j = min(max(j, 0), S - 1);
            *(uint2*)&KVh[row * 64 + c4] = *(const uint2*)&g_qkv[(size_t)j * RS + koff + c4];
        }
        __syncthreads();
        float a[4][4];
#pragma unroll
        for (int i = 0; i < 4; ++i)
#pragma unroll
            for (int j = 0; j < 4; ++j) a[i][j] = 0.f;
#pragma unroll
        for (int d = 0; d < 64; d += 4) {
            float4 qv[4], kv[4];
#pragma unroll
            for (int i = 0; i < 4; ++i) {
                qv[i] = *(const float4*)&Qs[(ttq + i) * 64 + d];
                uint2 u = *(const uint2*)&KVh[(ttj + i) * 64 + d];
                float2 k0 = __half22float2(*(__half2*)&u.x);
                float2 k1 = __half22float2(*(__half2*)&u.y);
                kv[i] = make_float4(k0.x, k0.y, k1.x, k1.y);
            }
#pragma unroll
            for (int i = 0; i < 4; ++i)
#pragma unroll
                for (int j = 0; j < 4; ++j)
                    a[i][j] += qv[i].x * kv[j].x + qv[i].y * kv[j].y +
                               qv[i].z * kv[j].z + qv[i].w * kv[j].w;
        }
#pragma unroll
        for (int i = 0; i < 4; ++i)
#pragma unroll
            for (int j = 0; j < 4; ++j) {
                int qq = ttq + i;
                int jj = jt * 64 + ttj + j;
                int jg = jbase + jj;
                int qg = q0 + qq;
                bool ok = (jg >= 0) && (jg < S) && (abs(qg - jg) <= HALFW);
                sc[qq * SCP + jj] = ok ? a[i][j] * ATT_SCALE : -1e30f;
            }
    }
    __syncthreads();

    // ---- softmax ----
    const int wid = tid >> 5, lane = tid & 31;
    for (int r = 0; r < 8; ++r) {
        int q = wid * 8 + r;
        float m = -1e30f;
        for (int j = lane; j < JW; j += 32) m = fmaxf(m, sc[q * SCP + j]);
#pragma unroll
        for (int off = 16; off > 0; off >>= 1) m = fmaxf(m, __shfl_xor_sync(0xffffffffu, m, off));
        float s = 0.f;
        for (int j = lane; j < JW; j += 32) {
            float e = __expf(sc[q * SCP + j] - m);
            sc[q * SCP + j] = e;
            s += e;
        }
#pragma unroll
        for (int off = 16; off > 0; off >>= 1) s += __shfl_xor_sync(0xffffffffu, s, off);
        if (lane == 0) invl[q] = 1.0f / s;
    }
    __syncthreads();

    // ---- AV ----
    float o[4][4];
#pragma unroll
    for (int i = 0; i < 4; ++i)
#pragma unroll
        for (int j = 0; j < 4; ++j) o[i][j] = 0.f;
#pragma unroll 1
    for (int jt = 0; jt < 5; ++jt) {
        __syncthreads();
        for (int i = tid; i < TQ * 16; i += 256) {
            int row = i >> 4, c4 = (i & 15) * 4;
            int j = jbase + jt * 64 + row;
            j = min(max(j, 0), S - 1);
            *(uint2*)&KVh[row * 64 + c4] = *(const uint2*)&g_qkv[(size_t)j * RS + voff + c4];
        }
        __syncthreads();
#pragma unroll 4
        for (int jj = 0; jj < 64; ++jj) {
            uint2 u = *(const uint2*)&KVh[jj * 64 + ttj];
            float2 v0 = __half22float2(*(__half2*)&u.x);
            float2 v1 = __half22float2(*(__half2*)&u.y);
            float p[4];
#pragma unroll
            for (int i = 0; i < 4; ++i) p[i] = sc[(ttq + i) * SCP + jt * 64 + jj];
#pragma unroll
            for (int i = 0; i < 4; ++i) {
                o[i][0] += p[i] * v0.x;
                o[i][1] += p[i] * v0.y;
                o[i][2] += p[i] * v1.x;
                o[i][3] += p[i] * v1.y;
            }
        }
    }
#pragma unroll
    for (int i = 0; i < 4; ++i) {
        int q = ttq + i;
        float il = invl[q];
        uint32_t h0 = pack_half2(o[i][0] * il, o[i][1] * il);
        uint32_t h1 = pack_half2(o[i][2] * il, o[i][3] * il);
        *(uint2*)&g_att[(size_t)(q0 + q) * D + qoff + ttj] = make_uint2(h0, h1);
    }
}

// ---------------- host ----------------
extern "C" void kernel_launch(void* const* d_in, const int* in_sizes, int n_in,
                              void* d_out, int out_size) {
    const int*   ids   = (const int*)  d_in[0];
    const float* emb   = (const float*)d_in[1];
    const float* pos   = (const float*)d_in[2];
    const float* wq    = (const float*)d_in[3];
    const float* bq    = (const float*)d_in[4];
    const float* wk    = (const float*)d_in[5];
    const float* bk    = (const float*)d_in[6];
    const float* wv    = (const float*)d_in[7];
    const float* bv    = (const float*)d_in[8];
    const float* wo    = (const float*)d_in[9];
    const float* bo    = (const float*)d_in[10];
    const float* w1    = (const float*)d_in[11];
    const float* b1    = (const float*)d_in[12];
    const float* w2    = (const float*)d_in[13];
    const float* b2    = (const float*)d_in[14];
    const float* ln1_g = (const float*)d_in[15];
    const float* ln1_b = (const float*)d_in[16];
    const float* ln2_g = (const float*)d_in[17];
    const float* ln2_b = (const float*)d_in[18];
    const float* out_g = (const float*)d_in[19];
    const float* out_b = (const float*)d_in[20];
    float* logits = (float*)d_out;

    float *x, *bqkv;
    __half *h, *qkv, *att, *ffn, *wT, *embT;
    cudaGetSymbolAddress((void**)&x,    g_x);
    cudaGetSymbolAddress((void**)&h,    g_h);
    cudaGetSymbolAddress((void**)&qkv,  g_qkv);
    cudaGetSymbolAddress((void**)&att,  g_att);
    cudaGetSymbolAddress((void**)&ffn,  g_ffn);
    cudaGetSymbolAddress((void**)&wT,   g_wT);
    cudaGetSymbolAddress((void**)&embT, g_embT);
    cudaGetSymbolAddress((void**)&bqkv, g_bqkv);

    const int BIG_SM = BSTW * 4 * BNSTG;                              // 81920 B
    const int SM64  = (BM + 64) * PADW * 4 * NSTG;                    // 82944 B
    const int ATTN_SM = (4096 + 2048 + 64 * SCP + 64) * 4;            // 107,792 B -> 2 CTAs/SM
    cudaFuncSetAttribute(mma_gemm_big<true,  true,  false, false>, cudaFuncAttributeMaxDynamicSharedMemorySize, BIG_SM);
    cudaFuncSetAttribute(mma_gemm_big<true,  true,  true,  false>, cudaFuncAttributeMaxDynamicSharedMemorySize, BIG_SM);
    cudaFuncSetAttribute(mma_gemm_big<false, false, false, false>, cudaFuncAttributeMaxDynamicSharedMemorySize, BIG_SM);
    cudaFuncSetAttribute(mma_gemm<64, false, true, false, true>,   cudaFuncAttributeMaxDynamicSharedMemorySize, SM64);
    cudaFuncSetAttribute(attn_tiled, cudaFuncAttributeMaxDynamicSharedMemorySize, ATTN_SM);

    prep_all<<<TP_END, 256>>>(wq, wk, wv, wo, w1, w2, emb, bq, bk, bv);
    embed_kernel<<<(S * D + 255) / 256, 256>>>(ids, emb, pos);

    for (int l = 0; l < NL; ++l) {
        __half* base = wT + (size_t)l * 12 * MB_ELT;

        ln_kernel<<<S, 256>>>(x, h, ln1_g + l * D, ln1_b + l * D);

        // qkv (grid 16x24, 128 thr)
        mma_gemm_big<true, true, false, false><<<dim3(S / BBM, 3 * D / BBN), 128, BIG_SM>>>(
            h, base + 0 * MB_ELT, bqkv + (size_t)l * 3 * D, nullptr, qkv, 3 * D, D);

        attn_tiled<<<dim3(S / TQ, H), 256, ATTN_SM>>>();

        mma_gemm<64, false, true, false, true><<<dim3(S / BM, D / 64), 256, SM64>>>(
            att, base + 3 * MB_ELT, bo + (size_t)l * D, x, x, D, D);

        ln_kernel<<<S, 256>>>(x, h, ln2_g + l * D, ln2_b + l * D);

        mma_gemm_big<true, true, true, false><<<dim3(S / BBM, DF / BBN), 128, BIG_SM>>>(
            h, base + 4 * MB_ELT, b1 + (size_t)l * DF, nullptr, ffn, DF, D);

        mma_gemm<64, false, true, false, true><<<dim3(S / BM, D / 64), 256, SM64>>>(
            ffn, base + 8 * MB_ELT, b2 + (size_t)l * D, x, x, D, DF);
    }

    ln_kernel<<<S, 256>>>(x, h, out_g, out_b);

    mma_gemm_big<false, false, false, false><<<dim3(S / BBM, VOCAB / BBN), 128, BIG_SM>>>(
        h, embT, nullptr, nullptr, logits, VOCAB, D);
}

// round 15
// speedup vs baseline: 1.2535x; 1.0378x over previous
#include <cuda_runtime.h>
#include <cuda_fp16.h>
#include <math.h>
#include <stdint.h>

// ---------------- problem constants ----------------
#define S 2048
#define D 1024
#define H 16
#define HD 64
#define DF 4096
#define NL 2
#define VOCAB 32000
#define HALFW 128
#define ATT_SCALE 0.125f
#define LN_EPS 1e-5f
#define MB_ELT (1024*1024)

// ---------------- scratch (device globals) ----------------
__device__ float  g_x[S * D];
__device__ __half g_h[S * D];
__device__ __half g_qkv[S * 3 * D];
__device__ __half g_att[S * D];
__device__ __half g_ffn[S * DF];
__device__ __half g_wT[NL * 12 * MB_ELT];
__device__ __half g_embT[VOCAB * D];
__device__ float  g_bqkv[NL * 3 * D];

// ---------------- helpers ----------------
__device__ __forceinline__ uint32_t smem_u32(const void* p) {
    uint32_t a;
    asm("{ .reg .u64 t; cvta.to.shared.u64 t, %1; cvt.u32.u64 %0, t; }" : "=r"(a) : "l"(p));
    return a;
}
__device__ __forceinline__ void cp16(uint32_t dst, const void* src) {
    asm volatile("cp.async.cg.shared.global [%0], [%1], 16;" :: "r"(dst), "l"(src));
}
__device__ __forceinline__ void cp_commit() {
    asm volatile("cp.async.commit_group;" ::: "memory");
}
template<int N>
__device__ __forceinline__ void cp_wait() {
    asm volatile("cp.async.wait_group %0;" :: "n"(N) : "memory");
}
__device__ __forceinline__ void ldsm_x4(uint32_t* r, uint32_t addr) {
    asm volatile("ldmatrix.sync.aligned.m8n8.x4.shared.b16 {%0,%1,%2,%3}, [%4];"
        : "=r"(r[0]), "=r"(r[1]), "=r"(r[2]), "=r"(r[3]) : "r"(addr));
}
__device__ __forceinline__ void mma_f16(float* c, const uint32_t* a, const uint32_t* b) {
    asm volatile(
        "mma.sync.aligned.m16n8k16.row.col.f32.f16.f16.f32 "
        "{%0,%1,%2,%3}, {%4,%5,%6,%7}, {%8,%9}, {%0,%1,%2,%3};"
        : "+f"(c[0]), "+f"(c[1]), "+f"(c[2]), "+f"(c[3])
        : "r"(a[0]), "r"(a[1]), "r"(a[2]), "r"(a[3]), "r"(b[0]), "r"(b[1]));
}
__device__ __forceinline__ float gelu_exact(float v) {
    return 0.5f * v * (1.0f + erff(v * 0.70710678118654752f));
}
__device__ __forceinline__ uint32_t pack_half2(float a, float b) {
    __half2 h = __floats2half2_rn(a, b);
    return *(uint32_t*)&h;
}

// ======= BIG GEMM (R11 config): 128 thr, 4 warps of 64x64, BKT=32, NSTG=4, reg dbuf =====
#define BBM 128
#define BBN 128
#define BBK 32
#define BPADW 20
#define BNSTG 4
#define BSTW ((BBM + BBN) * BPADW)

template<bool OUT_HALF, bool HAS_BIAS, bool DO_GELU, bool DO_RES>
__global__ __launch_bounds__(128, 2) void mma_gemm_big(
    const __half* __restrict__ A, const __half* __restrict__ B,
    const float* __restrict__ bias, const float* __restrict__ res,
    void* __restrict__ Cout, int N_total, int K_total)
{
    extern __shared__ __align__(16) uint32_t smw[];

    const int tid = threadIdx.x;
    const int bm = blockIdx.x * BBM;
    const int bn = blockIdx.y * BBN;
    const int wid = tid >> 5, lane = tid & 31;
    const int wm = (wid & 1) * 64;
    const int wn = (wid >> 1) * 64;
    const int grp = lane >> 2, tig = lane & 3;

    const uint32_t a_base = ((uint32_t)(wm + (lane & 15)) * BPADW + ((lane >> 4) & 1) * 4) * 4;
    const uint32_t b_base = ((uint32_t)(wn + ((lane >> 4) & 1) * 8 + (lane & 7)) * BPADW + ((lane >> 3) & 1) * 4) * 4;

    float acc[4][8][4];
#pragma unroll
    for (int i = 0; i < 4; ++i)
#pragma unroll
        for (int j = 0; j < 8; ++j)
#pragma unroll
            for (int q = 0; q < 4; ++q) acc[i][j][q] = 0.f;

    uint32_t af[2][4][4];
    uint32_t bf[2][8][2];

    const int nIter = K_total / BBK;

    auto fill = [&](int st, int k0) {
        uint32_t* Ast = smw + st * BSTW;
        uint32_t* Bst = Ast + BBM * BPADW;
#pragma unroll
        for (int i = 0; i < 4; ++i) {
            int id = tid + i * 128;
            int row = id >> 2, c = id & 3;
            cp16(smem_u32(Ast + row * BPADW + c * 4), A + (size_t)(bm + row) * K_total + k0 + c * 8);
        }
#pragma unroll
        for (int i = 0; i < 4; ++i) {
            int id = tid + i * 128;
            int row = id >> 2, c = id & 3;
            cp16(smem_u32(Bst + row * BPADW + c * 4), B + (size_t)(bn + row) * K_total + k0 + c * 8);
        }
    };

    auto load_frags = [&](int b, int st, int ks) {
        const uint32_t sa = smem_u32(smw + st * BSTW) + a_base + ks * 32;
        const uint32_t sb = smem_u32(smw + st * BSTW + BBM * BPADW) + b_base + ks * 32;
#pragma unroll
        for (int mt = 0; mt < 4; ++mt)
            ldsm_x4(af[b][mt], sa + (uint32_t)(mt * 16 * BPADW * 4));
#pragma unroll
        for (int p = 0; p < 4; ++p) {
            uint32_t r[4];
            ldsm_x4(r, sb + (uint32_t)(p * 16 * BPADW * 4));
            bf[b][2 * p][0] = r[0]; bf[b][2 * p][1] = r[1];
            bf[b][2 * p + 1][0] = r[2]; bf[b][2 * p + 1][1] = r[3];
        }
    };

    // prologue: fill stages 0..2
#pragma unroll
    for (int s = 0; s < BNSTG - 1; ++s) {
        fill(s, s * BBK);
        cp_commit();
    }
    cp_wait<2>();
    __syncthreads();
    load_frags(0, 0, 0);
    int buf = 0;

    for (int c = 0; c < nIter; ++c) {
        cp_wait<1>();
        __syncthreads();

        int nk = c + BNSTG - 1;
        if (nk < nIter) fill(nk % BNSTG, nk * BBK);
        cp_commit();

#pragma unroll
        for (int ks = 0; ks < 2; ++ks) {
            if (!(c == nIter - 1 && ks == 1)) {
                int pc  = (ks == 1) ? c + 1 : c;
                int pks = (ks == 1) ? 0 : 1;
                load_frags(buf ^ 1, pc % BNSTG, pks);
            }
#pragma unroll
            for (int mt = 0; mt < 4; ++mt)
#pragma unroll
                for (int nt = 0; nt < 8; ++nt)
                    mma_f16(acc[mt][nt], af[buf][mt], bf[buf][nt]);
            buf ^= 1;
        }
    }

    // epilogue
#pragma unroll
    for (int mt = 0; mt < 4; ++mt) {
        const int r0 = bm + wm + mt * 16 + grp;
#pragma unroll
        for (int nt = 0; nt < 8; ++nt) {
            const int cn = bn + wn + nt * 8 + tig * 2;
#pragma unroll
            for (int hh = 0; hh < 2; ++hh) {
                const int row = r0 + hh * 8;
                float v0 = acc[mt][nt][hh * 2 + 0];
                float v1 = acc[mt][nt][hh * 2 + 1];
                if (HAS_BIAS) { v0 += __ldg(&bias[cn]); v1 += __ldg(&bias[cn + 1]); }
                if (DO_GELU) { v0 = gelu_exact(v0); v1 = gelu_exact(v1); }
                if (DO_RES) {
                    const float2 rv = *(const float2*)(res + (size_t)row * N_total + cn);
                    v0 += rv.x; v1 += rv.y;
                }
                if (OUT_HALF) {
                    uint32_t hv = pack_half2(v0, v1);
                    *(uint32_t*)((__half*)Cout + (size_t)row * N_total + cn) = hv;
                } else {
                    *(float2*)((float*)Cout + (size_t)row * N_total + cn) = make_float2(v0, v1);
                }
            }
        }
    }
}

// ================= SMALL GEMM (wo/w2): unchanged (proven config) ====
#define BM 128
#define BKT 64
#define PADW 36
#define NSTG 3

template<int BNT, bool OUT_HALF, bool HAS_BIAS, bool DO_GELU, bool DO_RES>
__global__ __launch_bounds__(256, 2) void mma_gemm(
    const __half* __restrict__ A, const __half* __restrict__ B,
    const float* __restrict__ bias, const float* __restrict__ res,
    void* __restrict__ Cout, int N_total, int K_total)
{
    constexpr int NT = (BNT == 128) ? 8 : 4;
    constexpr int NP = NT / 2;
    constexpr int WNW = (BNT == 128) ? 64 : 32;
    constexpr int STW = (BM + BNT) * PADW;

    extern __shared__ __align__(16) uint32_t smw[];

    const int tid = threadIdx.x;
    const int bm = blockIdx.x * BM;
    const int bn = blockIdx.y * BNT;
    const int wid = tid >> 5, lane = tid & 31;
    const int wm = (wid & 3) * 32;
    const int wn = (wid >> 2) * WNW;
    const int grp = lane >> 2, tig = lane & 3;

    const uint32_t a_base = ((uint32_t)(wm + (lane & 15)) * PADW + ((lane >> 4) & 1) * 4) * 4;
    const uint32_t b_base = ((uint32_t)(wn + ((lane >> 4) & 1) * 8 + (lane & 7)) * PADW + ((lane >> 3) & 1) * 4) * 4;

    float acc[2][NT][4];
#pragma unroll
    for (int i = 0; i < 2; ++i)
#pragma unroll
        for (int j = 0; j < NT; ++j)
#pragma unroll
            for (int q = 0; q < 4; ++q) acc[i][j][q] = 0.f;

    const int nIter = K_total / BKT;

    auto fill = [&](int st, int k0) {
        uint32_t* Ast = smw + st * STW;
        uint32_t* Bst = Ast + BM * PADW;
#pragma unroll
        for (int i = 0; i < 4; ++i) {
            int id = tid + i * 256;
            int row = id >> 3, c = id & 7;
            cp16(smem_u32(Ast + row * PADW + c * 4), A + (size_t)(bm + row) * K_total + k0 + c * 8);
        }
#pragma unroll
        for (int i = 0; i < BNT / 32; ++i) {
            int id = tid + i * 256;
            int row = id >> 3, c = id & 7;
            cp16(smem_u32(Bst + row * PADW + c * 4), B + (size_t)(bn + row) * K_total + k0 + c * 8);
        }
    };

#pragma unroll
    for (int s = 0; s < NSTG - 1; ++s) {
        fill(s, s * BKT);
        cp_commit();
    }

    for (int c = 0; c < nIter; ++c) {
        cp_wait<NSTG - 2>();
        __syncthreads();

        int nk = c + NSTG - 1;
        if (nk < nIter) fill(nk % NSTG, nk * BKT);
        cp_commit();

        const uint32_t sa = smem_u32(smw + (c % NSTG) * STW) + a_base;
        const uint32_t sb = smem_u32(smw + (c % NSTG) * STW + BM * PADW) + b_base;
#pragma unroll
        for (int ks = 0; ks < 4; ++ks) {
            uint32_t af[2][4];
#pragma unroll
            for (int mt = 0; mt < 2; ++mt)
                ldsm_x4(af[mt], sa + (uint32_t)(mt * 16 * PADW * 4 + ks * 32));
            uint32_t bfr[NT][2];
#pragma unroll
            for (int p = 0; p < NP; ++p) {
                uint32_t r[4];
                ldsm_x4(r, sb + (uint32_t)(p * 16 * PADW * 4 + ks * 32));
                bfr[2 * p][0] = r[0]; bfr[2 * p][1] = r[1];
                bfr[2 * p + 1][0] = r[2]; bfr[2 * p + 1][1] = r[3];
            }
#pragma unroll
            for (int mt = 0; mt < 2; ++mt)
#pragma unroll
                for (int nt = 0; nt < NT; ++nt)
                    mma_f16(acc[mt][nt], af[mt], bfr[nt]);
        }
    }

#pragma unroll
    for (int mt = 0; mt < 2; ++mt) {
        const int r0 = bm + wm + mt * 16 + grp;
#pragma unroll
        for (int nt = 0; nt < NT; ++nt) {
            const int cn = bn + wn + nt * 8 + tig * 2;
#pragma unroll
            for (int hh = 0; hh < 2; ++hh) {
                const int row = r0 + hh * 8;
                float v0 = acc[mt][nt][hh * 2 + 0];
                float v1 = acc[mt][nt][hh * 2 + 1];
                if (HAS_BIAS) { v0 += __ldg(&bias[cn]); v1 += __ldg(&bias[cn + 1]); }
                if (DO_GELU) { v0 = gelu_exact(v0); v1 = gelu_exact(v1); }
                if (DO_RES) {
                    const float2 rv = *(const float2*)(res + (size_t)row * N_total + cn);
                    v0 += rv.x; v1 += rv.y;
                }
                if (OUT_HALF) {
                    uint32_t hv = pack_half2(v0, v1);
                    *(uint32_t*)((__half*)Cout + (size_t)row * N_total + cn) = hv;
                } else {
                    *(float2*)((float*)Cout + (size_t)row * N_total + cn) = make_float2(v0, v1);
                }
            }
        }
    }
}

// ---------------- fused prep ----------------
#define TP_W  24576
#define TP_E  56576
#define TP_END 56600

__global__ __launch_bounds__(256) void prep_all(
    const float* __restrict__ wq, const float* __restrict__ wk,
    const float* __restrict__ wv, const float* __restrict__ wo,
    const float* __restrict__ w1, const float* __restrict__ w2,
    const float* __restrict__ emb,
    const float* __restrict__ bq, const float* __restrict__ bk,
    const float* __restrict__ bv)
{
    const int b = blockIdx.x;
    const int tid = threadIdx.x;

    if (b < TP_W) {
        __shared__ float t[32][33];
        const int l = b / 12288;
        const int r = b % 12288;
        const float* src;
        __half* dst;
        int R, C, tile;
        __half* base = g_wT + (size_t)l * 12 * MB_ELT;
        if (r < 4096) {
            int w = r >> 10;
            tile = r & 1023;
            R = D; C = D;
            src = (w == 0 ? wq : w == 1 ? wk : w == 2 ? wv : wo) + (size_t)l * D * D;
            dst = base + (size_t)w * MB_ELT;
        } else if (r < 8192) {
            tile = r - 4096;
            R = D; C = DF;
            src = w1 + (size_t)l * D * DF;
            dst = base + 4 * MB_ELT;
        } else {
            tile = r - 8192;
            R = DF; C = D;
            src = w2 + (size_t)l * DF * D;
            dst = base + 8 * MB_ELT;
        }
        const int tc = C >> 5;
        const int r0 = (tile / tc) * 32;
        const int c0 = (tile % tc) * 32;
        const int x = tid & 31, y = tid >> 5;
#pragma unroll
        for (int i = y; i < 32; i += 8) t[i][x] = src[(size_t)(r0 + i) * C + c0 + x];
        __syncthreads();
#pragma unroll
        for (int i = y; i < 32; i += 8)
            dst[(size_t)(c0 + i) * R + r0 + x] = __float2half_rn(t[x][i]);
    } else if (b < TP_E) {
        size_t i0 = (size_t)(b - TP_W) * 1024 + tid * 4;
        float4 v = *(const float4*)(emb + i0);
        uint32_t h0 = pack_half2(v.x, v.y);
        uint32_t h1 = pack_half2(v.z, v.w);
        *(uint2*)(g_embT + i0) = make_uint2(h0, h1);
    } else {
        int idx = (b - TP_E) * 256 + tid;
        if (idx < NL * 3 * D) {
            int l = idx / (3 * D);
            int i = idx % (3 * D);
            float v = (i < D) ? bq[l * D + i] : (i < 2 * D) ? bk[l * D + i - D] : bv[l * D + i - 2 * D];
            g_bqkv[idx] = v;
        }
    }
}

// ---------------- small kernels ----------------
__global__ void embed_kernel(const int* __restrict__ ids,
                             const float* __restrict__ emb,
                             const float* __restrict__ pos) {
    int idx = blockIdx.x * blockDim.x + threadIdx.x;
    if (idx >= S * D) return;
    int s = idx >> 10;
    int d = idx & (D - 1);
    g_x[idx] = emb[(size_t)ids[s] * D + d] + pos[idx];
}

__global__ __launch_bounds__(256) void ln_kernel(const float* __restrict__ x,
                                                 __half* __restrict__ out,
                                                 const float* __restrict__ g,
                                                 const float* __restrict__ b) {
    __shared__ float rs[256], rs2[256];
    int row = blockIdx.x;
    int t = threadIdx.x;
    const float* xr = x + (size_t)row * D;
    float s = 0.f, s2 = 0.f;
#pragma unroll
    for (int i = t; i < D; i += 256) { float v = xr[i]; s += v; s2 += v * v; }
    rs[t] = s; rs2[t] = s2;
    __syncthreads();
    for (int off = 128; off > 0; off >>= 1) {
        if (t < off) { rs[t] += rs[t + off]; rs2[t] += rs2[t + off]; }
        __syncthreads();
    }
    float mu = rs[0] * (1.0f / D);
    float var = rs2[0] * (1.0f / D) - mu * mu;
    float inv = rsqrtf(var + LN_EPS);
    __half* orow = out + (size_t)row * D;
#pragma unroll
    for (int i = t; i < D; i += 256)
        orow[i] = __float2half_rn((xr[i] - mu) * inv * g[i] + b[i]);
}

// ---------------- one-pass local attention (online softmax, 4 CTAs/SM) ----------------
// smem: Qs f32[64*64] | Kh h[64*64] | Vh h[64*64] | sp f32[64*68]  = ~49.2 KB
#define TQ 64
#define SPW 68

__global__ __launch_bounds__(256, 4) void attn_tiled() {
    extern __shared__ __align__(16) float asm_[];
    float*  Qs = asm_;                             // 4096 floats
    __half* Kh = (__half*)(asm_ + 4096);           // 4096 halfs (2048 floats)
    __half* Vh = (__half*)(asm_ + 4096 + 2048);    // 4096 halfs
    float*  sp = asm_ + 4096 + 2048 + 2048;        // 64*SPW floats

    const int q0 = blockIdx.x * TQ;
    const int head = blockIdx.y;
    const int tid = threadIdx.x;
    const int RS = 3 * D;
    const int qoff = head * HD, koff = D + head * HD, voff = 2 * D + head * HD;
    const int jbase = q0 - HALFW;

    const int ttq = (tid >> 4) << 2;   // q row group
    const int ttj = (tid & 15) << 2;   // j / d column group

    // load Q tile (half -> float)
    for (int i = tid; i < TQ * 16; i += 256) {
        int row = i >> 4, c4 = (i & 15) * 4;
        uint2 u = *(const uint2*)&g_qkv[(size_t)(q0 + row) * RS + qoff + c4];
        float2 f0 = __half22float2(*(__half2*)&u.x);
        float2 f1 = __half22float2(*(__half2*)&u.y);
        float* dst = &Qs[row * 64 + c4];
        dst[0] = f0.x; dst[1] = f0.y; dst[2] = f1.x; dst[3] = f1.y;
    }

    float m[4], sden[4], o[4][4];
#pragma unroll
    for (int i = 0; i < 4; ++i) {
        m[i] = -1e30f; sden[i] = 0.f;
#pragma unroll
        for (int j = 0; j < 4; ++j) o[i][j] = 0.f;
    }

#pragma unroll 1
    for (int jt = 0; jt < 5; ++jt) {
        __syncthreads();   // previous AV done; safe to overwrite Kh/Vh/sp
        // load K and V tiles (half, clamped row index; invalid cols masked later)
        for (int i = tid; i < TQ * 16; i += 256) {
            int row = i >> 4, c4 = (i & 15) * 4;
            int j = jbase + jt * 64 + row;
            j = min(max(j, 0), S - 1);
            *(uint2*)&Kh[row * 64 + c4] = *(const uint2*)&g_qkv[(size_t)j * RS + koff + c4];
            *(uint2*)&Vh[row * 64 + c4] = *(const uint2*)&g_qkv[(size_t)j * RS + voff + c4];
        }
        __syncthreads();

        // scores a[4][4] = Q . K
        float a[4][4];
#pragma unroll
        for (int i = 0; i < 4; ++i)
#pragma unroll
            for (int j = 0; j < 4; ++j) a[i][j] = 0.f;
#pragma unroll
        for (int d = 0; d < 64; d += 4) {
            float4 qv[4], kv[4];
#pragma unroll
            for (int i = 0; i < 4; ++i) {
                qv[i] = *(const float4*)&Qs[(ttq + i) * 64 + d];
                uint2 u = *(const uint2*)&Kh[(ttj + i) * 64 + d];
                float2 k0 = __half22float2(*(__half2*)&u.x);
                float2 k1 = __half22float2(*(__half2*)&u.y);
                kv[i] = make_float4(k0.x, k0.y, k1.x, k1.y);
            }
#pragma unroll
            for (int i = 0; i < 4; ++i)
#pragma unroll
                for (int j = 0; j < 4; ++j)
                    a[i][j] += qv[i].x * kv[j].x + qv[i].y * kv[j].y +
                               qv[i].z * kv[j].z + qv[i].w * kv[j].w;
        }

        // mask + scale; compute per-row tile max
        bool okm[4][4];
        float tmax[4];
#pragma unroll
        for (int i = 0; i < 4; ++i) {
            tmax[i] = -1e30f;
            int qg = q0 + ttq + i;
#pragma unroll
            for (int j = 0; j < 4; ++j) {
                int jg = jbase + jt * 64 + ttj + j;
                bool ok = (jg >= 0) && (jg < S) && (abs(qg - jg) <= HALFW);
                okm[i][j] = ok;
                a[i][j] = ok ? a[i][j] * ATT_SCALE : -1e30f;
                tmax[i] = fmaxf(tmax[i], a[i][j]);
            }
        }
        // reduce max over the 16 threads sharing each q-row (xor within 16-lane group)
#pragma unroll
        for (int off = 8; off > 0; off >>= 1)
#pragma unroll
            for (int i = 0; i < 4; ++i)
                tmax[i] = fmaxf(tmax[i], __shfl_xor_sync(0xffffffffu, tmax[i], off));

        // online update
        float p[4][4], tsum[4];
#pragma unroll
        for (int i = 0; i < 4; ++i) {
            float mnew = fmaxf(m[i], tmax[i]);
            float r = __expf(m[i] - mnew);
            m[i] = mnew;
            tsum[i] = 0.f;
#pragma unroll
            for (int j = 0; j < 4; ++j) {
                float e = okm[i][j] ? __expf(a[i][j] - mnew) : 0.f;
                p[i][j] = e;
                tsum[i] += e;
            }
            sden[i] = sden[i] * r + 0.f;   // tile sum added after cross-thread reduce
#pragma unroll
            for (int j = 0; j < 4; ++j) o[i][j] *= r;
            // stash r-applied denom add below
            // (tsum reduced next)
            a[i][0] = r;  // reuse a[i][0] slot to carry r? no — keep separate
        }
        // reduce tile sums across the 16 threads
#pragma unroll
        for (int off = 8; off > 0; off >>= 1)
#pragma unroll
            for (int i = 0; i < 4; ++i)
                tsum[i] += __shfl_xor_sync(0xffffffffu, tsum[i], off);
#pragma unroll
        for (int i = 0; i < 4; ++i) sden[i] += tsum[i];

        // write p to sp for layout switch (q,j) -> (q,d)
#pragma unroll
        for (int i = 0; i < 4; ++i)
            *(float4*)&sp[(ttq + i) * SPW + ttj] = make_float4(p[i][0], p[i][1], p[i][2], p[i][3]);
        __syncthreads();

        // AV accumulate: thread owns d-cols ttj..ttj+3 of q-rows ttq..ttq+3
#pragma unroll 4
        for (int jj = 0; jj < 64; ++jj) {
            uint2 u = *(const uint2*)&Vh[jj * 64 + ttj];
            float2 v0 = __half22float2(*(__half2*)&u.x);
            float2 v1 = __half22float2(*(__half2*)&u.y);
            float pr[4];
#pragma unroll
            for (int i = 0; i < 4; ++i) pr[i] = sp[(ttq + i) * SPW + jj];
#pragma unroll
            for (int i = 0; i < 4; ++i) {
                o[i][0] += pr[i] * v0.x;
                o[i][1] += pr[i] * v0.y;
                o[i][2] += pr[i] * v1.x;
                o[i][3] += pr[i] * v1.y;
            }
        }
    }

    // write out (normalize)
#pragma unroll
    for (int i = 0; i < 4; ++i) {
        int q = ttq + i;
        float il = 1.0f / sden[i];
        uint32_t h0 = pack_half2(o[i][0] * il, o[i][1] * il);
        uint32_t h1 = pack_half2(o[i][2] * il, o[i][3] * il);
        *(uint2*)&g_att[(size_t)(q0 + q) * D + qoff + ttj] = make_uint2(h0, h1);
    }
}

// ---------------- host ----------------
extern "C" void kernel_launch(void* const* d_in, const int* in_sizes, int n_in,
                              void* d_out, int out_size) {
    const int*   ids   = (const int*)  d_in[0];
    const float* emb   = (const float*)d_in[1];
    const float* pos   = (const float*)d_in[2];
    const float* wq    = (const float*)d_in[3];
    const float* bq    = (const float*)d_in[4];
    const float* wk    = (const float*)d_in[5];
    const float* bk    = (const float*)d_in[6];
    const float* wv    = (const float*)d_in[7];
    const float* bv    = (const float*)d_in[8];
    const float* wo    = (const float*)d_in[9];
    const float* bo    = (const float*)d_in[10];
    const float* w1    = (const float*)d_in[11];
    const float* b1    = (const float*)d_in[12];
    const float* w2    = (const float*)d_in[13];
    const float* b2    = (const float*)d_in[14];
    const float* ln1_g = (const float*)d_in[15];
    const float* ln1_b = (const float*)d_in[16];
    const float* ln2_g = (const float*)d_in[17];
    const float* ln2_b = (const float*)d_in[18];
    const float* out_g = (const float*)d_in[19];
    const float* out_b = (const float*)d_in[20];
    float* logits = (float*)d_out;

    float *x, *bqkv;
    __half *h, *qkv, *att, *ffn, *wT, *embT;
    cudaGetSymbolAddress((void**)&x,    g_x);
    cudaGetSymbolAddress((void**)&h,    g_h);
    cudaGetSymbolAddress((void**)&qkv,  g_qkv);
    cudaGetSymbolAddress((void**)&att,  g_att);
    cudaGetSymbolAddress((void**)&ffn,  g_ffn);
    cudaGetSymbolAddress((void**)&wT,   g_wT);
    cudaGetSymbolAddress((void**)&embT, g_embT);
    cudaGetSymbolAddress((void**)&bqkv, g_bqkv);

    const int BIG_SM = BSTW * 4 * BNSTG;                       // 81920 B
    const int SM64  = (BM + 64) * PADW * 4 * NSTG;             // 82944 B
    const int ATTN_SM = (4096 + 2048 + 2048 + 64 * SPW) * 4;   // 50,176 B -> 4 CTAs/SM
    cudaFuncSetAttribute(mma_gemm_big<true,  true,  false, false>, cudaFuncAttributeMaxDynamicSharedMemorySize, BIG_SM);
    cudaFuncSetAttribute(mma_gemm_big<true,  true,  true,  false>, cudaFuncAttributeMaxDynamicSharedMemorySize, BIG_SM);
    cudaFuncSetAttribute(mma_gemm_big<false, false, false, false>, cudaFuncAttributeMaxDynamicSharedMemorySize, BIG_SM);
    cudaFuncSetAttribute(mma_gemm<64, false, true, false, true>,   cudaFuncAttributeMaxDynamicSharedMemorySize, SM64);
    cudaFuncSetAttribute(attn_tiled, cudaFuncAttributeMaxDynamicSharedMemorySize, ATTN_SM);

    prep_all<<<TP_END, 256>>>(wq, wk, wv, wo, w1, w2, emb, bq, bk, bv);
    embed_kernel<<<(S * D + 255) / 256, 256>>>(ids, emb, pos);

    for (int l = 0; l < NL; ++l) {
        __half* base = wT + (size_t)l * 12 * MB_ELT;

        ln_kernel<<<S, 256>>>(x, h, ln1_g + l * D, ln1_b + l * D);

        // qkv (grid 16x24, 128 thr)
        mma_gemm_big<true, true, false, false><<<dim3(S / BBM, 3 * D / BBN), 128, BIG_SM>>>(
            h, base + 0 * MB_ELT, bqkv + (size_t)l * 3 * D, nullptr, qkv, 3 * D, D);

        attn_tiled<<<dim3(S / TQ, H), 256, ATTN_SM>>>();

        mma_gemm<64, false, true, false, true><<<dim3(S / BM, D / 64), 256, SM64>>>(
            att, base + 3 * MB_ELT, bo + (size_t)l * D, x, x, D, D);

        ln_kernel<<<S, 256>>>(x, h, ln2_g + l * D, ln2_b + l * D);

        mma_gemm_big<true, true, true, false><<<dim3(S / BBM, DF / BBN), 128, BIG_SM>>>(
            h, base + 4 * MB_ELT, b1 + (size_t)l * DF, nullptr, ffn, DF, D);

        mma_gemm<64, false, true, false, true><<<dim3(S / BM, D / 64), 256, SM64>>>(
            ffn, base + 8 * MB_ELT, b2 + (size_t)l * D, x, x, D, DF);
    }

    ln_kernel<<<S, 256>>>(x, h, out_g, out_b);

    mma_gemm_big<false, false, false, false><<<dim3(S / BBM, VOCAB / BBN), 128, BIG_SM>>>(
        h, embT, nullptr, nullptr, logits, VOCAB, D);
}